// round 14
// baseline (speedup 1.0000x reference)
#include <cuda_runtime.h>
#include <cstddef>

#define T_STEPS 8192
#define NRES    2048
#define DIN     64
#define DOUT    64
#define GBLK    128          // CTAs; 16 rows each
#define TPB     256
#define LEAK    0.3f
#define NOISE_L 0.01f
#define TILE_T  128

// ---------------- scratch (device globals: allocation-free) ----------------
__device__ float    g_drive [T_STEPS * NRES];   // 64 MB
__device__ float    g_states[T_STEPS * NRES];   // 64 MB
__device__ float    g_sbuf  [2][NRES];          // double-buffered reservoir state
__device__ unsigned g_ctr;                      // monotonic barrier counter

// ---------------- kernel 0: reset barrier + state (determinism) -------------
__global__ void init_kernel() {
    int i = blockIdx.x * blockDim.x + threadIdx.x;
    if (i < NRES) { g_sbuf[0][i] = 0.f; g_sbuf[1][i] = 0.f; }
    if (i == 0) g_ctr = 0u;
}

// ---------------- kernel 1: drive = u @ W_in^T + 0.01*noise -----------------
__global__ void drive_kernel(const float* __restrict__ u,
                             const float* __restrict__ noise,
                             const float* __restrict__ W_in) {
    __shared__ float4 u_sh[TILE_T * (DIN / 4)];
    const int n  = blockIdx.x * 256 + threadIdx.x;
    const int t0 = blockIdx.y * TILE_T;

    float4 w[DIN / 4];
    const float4* Wv = reinterpret_cast<const float4*>(W_in);
    #pragma unroll
    for (int j = 0; j < DIN / 4; j++) w[j] = Wv[(size_t)n * (DIN / 4) + j];

    const float4* uv = reinterpret_cast<const float4*>(u + (size_t)t0 * DIN);
    for (int i = threadIdx.x; i < TILE_T * (DIN / 4); i += 256) u_sh[i] = uv[i];
    __syncthreads();

    for (int t = 0; t < TILE_T; t++) {
        float acc = 0.f;
        #pragma unroll
        for (int j = 0; j < DIN / 4; j++) {
            float4 uu = u_sh[t * (DIN / 4) + j];
            acc += w[j].x * uu.x + w[j].y * uu.y + w[j].z * uu.z + w[j].w * uu.w;
        }
        size_t idx = (size_t)(t0 + t) * NRES + n;
        g_drive[idx] = acc + NOISE_L * noise[idx];
    }
}

// ---------------- kernel 2: persistent reservoir ----------------------------
// R12 structure (proven best): split-K, warp-private staging, warp-0 tail,
// 2 CTA barriers/step, single monotonic counter, 1 parked spinner per CTA.
// R14 cuts: (1) only the 64B g_sbuf publish precedes the release arrival —
// g_states store + drive prefetch moved after it; (2) tree-reduced tail;
// (3) relaxed polling with one trailing acquire fence.
__global__ void __launch_bounds__(TPB, 1) reservoir_kernel(const float* __restrict__ W) {
    __shared__ float s_sh[8][272];            // per-warp slab: 2x(128 data + 8 pad)
    __shared__ float red_sh[2][8][17];        // parity-buffered warp partials

    const int tid  = threadIdx.x;
    const int cta  = blockIdx.x;
    const int warp = tid >> 5;
    const int lane = tid & 31;
    const int row  = lane & 15;               // local row 0..15
    const int half = lane >> 4;               // 0: cols +0..127, 1: +128..255
    const int grow = cta * 16 + row;          // global row of my partial

    // W slice: row grow, cols [warp*256 + half*128, +128) -> 64 f32x2 regs
    const int c0 = warp * 256 + half * 128;
    const float4* Wv = reinterpret_cast<const float4*>(W + (size_t)grow * NRES + c0);
    unsigned long long wp[64];
    #pragma unroll
    for (int k = 0; k < 32; k++) {
        float4 a = Wv[k];
        wp[2*k]   = ((unsigned long long)__float_as_uint(a.y) << 32) | __float_as_uint(a.x);
        wp[2*k+1] = ((unsigned long long)__float_as_uint(a.w) << 32) | __float_as_uint(a.z);
    }

    const bool tail = (warp == 0) && (lane < 16);   // warp 0 lanes own the rows
    float sp   = 0.f;
    float dcur = 0.f;
    if (tail) dcur = g_drive[grow];

    float4* slab4 = reinterpret_cast<float4*>(s_sh[warp]);   // 272 floats = 68 f4
    const int rdbase = 34 * half;             // my half starts at f4 34*half

    #pragma unroll 1
    for (int t = 0; t < T_STEPS; t++) {
        // ---- warp-private stage: 2 coalesced 512B LDGs, STS, syncwarp ------
        const float4* sg = reinterpret_cast<const float4*>(g_sbuf[t & 1]) + warp * 64;
        float4 vA = __ldcg(sg + lane);
        float4 vB = __ldcg(sg + 32 + lane);
        slab4[lane]      = vA;
        slab4[34 + lane] = vB;
        __syncwarp();

        // ---- broadcast-LDS split-K partials (4 f32x2 chains) ---------------
        unsigned long long aA = 0, aB = 0, aC = 0, aD = 0;
        #pragma unroll
        for (int k = 0; k < 32; k += 2) {
            float4 sv  = slab4[rdbase + k];
            float4 sv2 = slab4[rdbase + k + 1];
            asm("{\n\t"
                ".reg .b64 p0, p1, p2, p3;\n\t"
                "mov.b64 p0, {%4, %5};\n\t"
                "mov.b64 p1, {%6, %7};\n\t"
                "mov.b64 p2, {%8, %9};\n\t"
                "mov.b64 p3, {%10, %11};\n\t"
                "fma.rn.f32x2 %0, %12, p0, %0;\n\t"
                "fma.rn.f32x2 %1, %13, p1, %1;\n\t"
                "fma.rn.f32x2 %2, %14, p2, %2;\n\t"
                "fma.rn.f32x2 %3, %15, p3, %3;\n\t"
                "}"
                : "+l"(aA), "+l"(aB), "+l"(aC), "+l"(aD)
                : "f"(sv.x), "f"(sv.y), "f"(sv.z), "f"(sv.w),
                  "f"(sv2.x), "f"(sv2.y), "f"(sv2.z), "f"(sv2.w),
                  "l"(wp[2*k]), "l"(wp[2*k+1]), "l"(wp[2*k+2]), "l"(wp[2*k+3]));
        }
        float e0, o0, e1, o1;
        asm("{\n\t.reg .b64 r0;\n\tadd.rn.f32x2 r0, %2, %3;\n\tmov.b64 {%0, %1}, r0;\n\t}"
            : "=f"(e0), "=f"(o0) : "l"(aA), "l"(aB));
        asm("{\n\t.reg .b64 r1;\n\tadd.rn.f32x2 r1, %2, %3;\n\tmov.b64 {%0, %1}, r1;\n\t}"
            : "=f"(e1), "=f"(o1) : "l"(aC), "l"(aD));
        float part = (e0 + o0) + (e1 + o1);              // my half's 128-col sum
        part += __shfl_xor_sync(0xffffffffu, part, 16);  // merge halves

        const int par = t & 1;
        if (lane < 16) red_sh[par][warp][row] = part;
        __syncthreads();                                 // bar B

        // ---- tail: warp 0's 16 lanes tree-reduce 8 warps, update, publish --
        float ns = 0.f;
        if (tail) {
            float p0 = red_sh[par][0][row], p1 = red_sh[par][1][row];
            float p2 = red_sh[par][2][row], p3 = red_sh[par][3][row];
            float p4 = red_sh[par][4][row], p5 = red_sh[par][5][row];
            float p6 = red_sh[par][6][row], p7 = red_sh[par][7][row];
            float sum = (((p0 + p1) + (p2 + p3)) + ((p4 + p5) + (p6 + p7))) + dcur;
            float z  = __expf(2.f * sum);                // tanh = 1 - 2/(e^2x+1)
            float th = 1.f - __fdividef(2.f, z + 1.f);
            ns = (1.f - LEAK) * sp + LEAK * th;
            sp = ns;
            g_sbuf[(t + 1) & 1][grow] = ns;              // ONLY store before release
        }
        __syncwarp();                                    // order warp-0 publishes

        // ---- arrival: release flushes just the 64B publish line ------------
        if (tid == 0)
            asm volatile("red.release.gpu.global.add.u32 [%0], 1;"
                         :: "l"(&g_ctr) : "memory");

        // ---- off-release-path work, overlaps the spin ----------------------
        if (tail) {
            __stcs(&g_states[(size_t)t * NRES + grow], ns);
            if (t + 1 < T_STEPS)
                dcur = g_drive[(size_t)(t + 1) * NRES + grow];
        }

        // ---- spin: relaxed polls + one acquire fence on success ------------
        if (tid == 0) {
            const unsigned target = (unsigned)(t + 1) * GBLK;
            unsigned c;
            do {
                asm volatile("ld.relaxed.gpu.global.u32 %0, [%1];"
                             : "=r"(c) : "l"(&g_ctr));
            } while (c < target);
            asm volatile("fence.acq_rel.gpu;" ::: "memory");
        }
        __syncthreads();                                 // bar D: release CTA
    }
}

// ---------------- kernel 3: out = states @ w_out^T + b_out ------------------
__global__ void proj_kernel(const float* __restrict__ w_out,
                            const float* __restrict__ b_out,
                            float* __restrict__ out) {
    __shared__ float s_sh[32][33];
    __shared__ float w_sh[DOUT][33];
    const int t0  = blockIdx.x * 32;
    const int tid = threadIdx.x;
    const int tx  = tid & 15;
    const int ty  = tid >> 4;
    float acc[2][4] = {};

    for (int kc = 0; kc < NRES; kc += 32) {
        for (int i = tid; i < 32 * 32; i += 256) {
            int r = i >> 5, k = i & 31;
            s_sh[r][k] = g_states[(size_t)(t0 + r) * NRES + kc + k];
        }
        for (int i = tid; i < DOUT * 32; i += 256) {
            int o = i >> 5, k = i & 31;
            w_sh[o][k] = w_out[(size_t)o * NRES + kc + k];
        }
        __syncthreads();
        for (int k = 0; k < 32; k++) {
            float sv[2], wv[4];
            #pragma unroll
            for (int i = 0; i < 2; i++) sv[i] = s_sh[ty * 2 + i][k];
            #pragma unroll
            for (int j = 0; j < 4; j++) wv[j] = w_sh[tx * 4 + j][k];
            #pragma unroll
            for (int i = 0; i < 2; i++)
                #pragma unroll
                for (int j = 0; j < 4; j++)
                    acc[i][j] += sv[i] * wv[j];
        }
        __syncthreads();
    }
    #pragma unroll
    for (int i = 0; i < 2; i++)
        #pragma unroll
        for (int j = 0; j < 4; j++)
            out[(size_t)(t0 + ty * 2 + i) * DOUT + tx * 4 + j] = acc[i][j] + b_out[tx * 4 + j];
}

// ---------------- launch ----------------------------------------------------
extern "C" void kernel_launch(void* const* d_in, const int* in_sizes, int n_in,
                              void* d_out, int out_size) {
    const float* u     = (const float*)d_in[0];  // (8192, 64)
    const float* noise = (const float*)d_in[1];  // (8192, 2048)
    const float* W_in  = (const float*)d_in[2];  // (2048, 64)
    const float* W     = (const float*)d_in[3];  // (2048, 2048)
    const float* w_out = (const float*)d_in[4];  // (64, 2048)
    const float* b_out = (const float*)d_in[5];  // (64,)
    float* out = (float*)d_out;                  // (8192, 64)

    init_kernel<<<NRES / 256, 256>>>();
    drive_kernel<<<dim3(NRES / 256, T_STEPS / TILE_T), 256>>>(u, noise, W_in);
    reservoir_kernel<<<GBLK, TPB>>>(W);
    proj_kernel<<<T_STEPS / 32, 256>>>(w_out, b_out, out);
}

// round 15
// speedup vs baseline: 1.0814x; 1.0814x over previous
#include <cuda_runtime.h>
#include <cstddef>

#define T_STEPS 8192
#define NRES    2048
#define DIN     64
#define DOUT    64
#define GBLK    128          // CTAs; 16 rows each
#define TPB     256
#define LEAK    0.3f
#define NOISE_L 0.01f
#define TILE_T  128

// ---------------- scratch (device globals: allocation-free) ----------------
__device__ float    g_drive [T_STEPS * NRES];   // 64 MB
__device__ float    g_states[T_STEPS * NRES];   // 64 MB
__device__ float    g_sbuf  [2][NRES];          // double-buffered reservoir state
__device__ unsigned g_ctr;                      // monotonic barrier counter

// ---------------- kernel 0: reset barrier + state (determinism) -------------
__global__ void init_kernel() {
    int i = blockIdx.x * blockDim.x + threadIdx.x;
    if (i < NRES) { g_sbuf[0][i] = 0.f; g_sbuf[1][i] = 0.f; }
    if (i == 0) g_ctr = 0u;
}

// ---------------- kernel 1: drive = u @ W_in^T + 0.01*noise -----------------
__global__ void drive_kernel(const float* __restrict__ u,
                             const float* __restrict__ noise,
                             const float* __restrict__ W_in) {
    __shared__ float4 u_sh[TILE_T * (DIN / 4)];
    const int n  = blockIdx.x * 256 + threadIdx.x;
    const int t0 = blockIdx.y * TILE_T;

    float4 w[DIN / 4];
    const float4* Wv = reinterpret_cast<const float4*>(W_in);
    #pragma unroll
    for (int j = 0; j < DIN / 4; j++) w[j] = Wv[(size_t)n * (DIN / 4) + j];

    const float4* uv = reinterpret_cast<const float4*>(u + (size_t)t0 * DIN);
    for (int i = threadIdx.x; i < TILE_T * (DIN / 4); i += 256) u_sh[i] = uv[i];
    __syncthreads();

    for (int t = 0; t < TILE_T; t++) {
        float acc = 0.f;
        #pragma unroll
        for (int j = 0; j < DIN / 4; j++) {
            float4 uu = u_sh[t * (DIN / 4) + j];
            acc += w[j].x * uu.x + w[j].y * uu.y + w[j].z * uu.z + w[j].w * uu.w;
        }
        size_t idx = (size_t)(t0 + t) * NRES + n;
        g_drive[idx] = acc + NOISE_L * noise[idx];
    }
}

// ---------------- kernel 2: persistent reservoir (R12, proven best) ---------
// Split-K: warp w owns cols [256w,256w+256); lane l: row l&15, half l>>4.
// Warp-private staging (2 coalesced LDGs + __syncwarp), broadcast-LDS FMAs,
// warp-0 tail, 2 CTA barriers/step, single monotonic counter with
// release-red arrival / acquire-ld spin, exactly 1 parked spinner per CTA.
// Sole change vs R12: tail reduce is a depth-3 add tree (no ordering change).
__global__ void __launch_bounds__(TPB, 1) reservoir_kernel(const float* __restrict__ W) {
    __shared__ float s_sh[8][272];            // per-warp slab: 2x(128 data + 8 pad)
    __shared__ float red_sh[2][8][17];        // parity-buffered warp partials

    const int tid  = threadIdx.x;
    const int cta  = blockIdx.x;
    const int warp = tid >> 5;
    const int lane = tid & 31;
    const int row  = lane & 15;               // local row 0..15
    const int half = lane >> 4;               // 0: cols +0..127, 1: +128..255
    const int grow = cta * 16 + row;          // global row of my partial

    // W slice: row grow, cols [warp*256 + half*128, +128) -> 64 f32x2 regs
    const int c0 = warp * 256 + half * 128;
    const float4* Wv = reinterpret_cast<const float4*>(W + (size_t)grow * NRES + c0);
    unsigned long long wp[64];
    #pragma unroll
    for (int k = 0; k < 32; k++) {
        float4 a = Wv[k];
        wp[2*k]   = ((unsigned long long)__float_as_uint(a.y) << 32) | __float_as_uint(a.x);
        wp[2*k+1] = ((unsigned long long)__float_as_uint(a.w) << 32) | __float_as_uint(a.z);
    }

    const bool tail = (warp == 0) && (lane < 16);   // warp 0 lanes own the rows
    float sp   = 0.f;
    float dcur = 0.f;
    if (tail) dcur = g_drive[grow];

    float4* slab4 = reinterpret_cast<float4*>(s_sh[warp]);   // 272 floats = 68 f4
    const int rdbase = 34 * half;             // my half starts at f4 34*half

    #pragma unroll 1
    for (int t = 0; t < T_STEPS; t++) {
        // ---- warp-private stage: 2 coalesced 512B LDGs, STS, syncwarp ------
        const float4* sg = reinterpret_cast<const float4*>(g_sbuf[t & 1]) + warp * 64;
        float4 vA = __ldcg(sg + lane);
        float4 vB = __ldcg(sg + 32 + lane);
        slab4[lane]      = vA;
        slab4[34 + lane] = vB;
        __syncwarp();

        // ---- broadcast-LDS split-K partials (4 f32x2 chains) ---------------
        unsigned long long aA = 0, aB = 0, aC = 0, aD = 0;
        #pragma unroll
        for (int k = 0; k < 32; k += 2) {
            float4 sv  = slab4[rdbase + k];
            float4 sv2 = slab4[rdbase + k + 1];
            asm("{\n\t"
                ".reg .b64 p0, p1, p2, p3;\n\t"
                "mov.b64 p0, {%4, %5};\n\t"
                "mov.b64 p1, {%6, %7};\n\t"
                "mov.b64 p2, {%8, %9};\n\t"
                "mov.b64 p3, {%10, %11};\n\t"
                "fma.rn.f32x2 %0, %12, p0, %0;\n\t"
                "fma.rn.f32x2 %1, %13, p1, %1;\n\t"
                "fma.rn.f32x2 %2, %14, p2, %2;\n\t"
                "fma.rn.f32x2 %3, %15, p3, %3;\n\t"
                "}"
                : "+l"(aA), "+l"(aB), "+l"(aC), "+l"(aD)
                : "f"(sv.x), "f"(sv.y), "f"(sv.z), "f"(sv.w),
                  "f"(sv2.x), "f"(sv2.y), "f"(sv2.z), "f"(sv2.w),
                  "l"(wp[2*k]), "l"(wp[2*k+1]), "l"(wp[2*k+2]), "l"(wp[2*k+3]));
        }
        float e0, o0, e1, o1;
        asm("{\n\t.reg .b64 r0;\n\tadd.rn.f32x2 r0, %2, %3;\n\tmov.b64 {%0, %1}, r0;\n\t}"
            : "=f"(e0), "=f"(o0) : "l"(aA), "l"(aB));
        asm("{\n\t.reg .b64 r1;\n\tadd.rn.f32x2 r1, %2, %3;\n\tmov.b64 {%0, %1}, r1;\n\t}"
            : "=f"(e1), "=f"(o1) : "l"(aC), "l"(aD));
        float part = (e0 + o0) + (e1 + o1);              // my half's 128-col sum
        part += __shfl_xor_sync(0xffffffffu, part, 16);  // merge halves

        const int par = t & 1;
        if (lane < 16) red_sh[par][warp][row] = part;
        __syncthreads();                                 // bar B

        // ---- tail: warp 0's 16 lanes tree-reduce 8 warps, update, publish --
        if (tail) {
            float p0 = red_sh[par][0][row], p1 = red_sh[par][1][row];
            float p2 = red_sh[par][2][row], p3 = red_sh[par][3][row];
            float p4 = red_sh[par][4][row], p5 = red_sh[par][5][row];
            float p6 = red_sh[par][6][row], p7 = red_sh[par][7][row];
            float sum = dcur + (((p0 + p1) + (p2 + p3)) + ((p4 + p5) + (p6 + p7)));
            float z  = __expf(2.f * sum);                // tanh = 1 - 2/(e^2x+1)
            float th = 1.f - __fdividef(2.f, z + 1.f);
            float ns = (1.f - LEAK) * sp + LEAK * th;
            sp = ns;
            g_sbuf[(t + 1) & 1][grow] = ns;              // coalesced 64B publish
            __stcs(&g_states[(size_t)t * NRES + grow], ns);
            if (t + 1 < T_STEPS)                         // prefetch under spin
                dcur = g_drive[(size_t)(t + 1) * NRES + grow];
        }
        __syncwarp();                                    // order warp-0 publishes

        // ---- monotonic grid barrier (release-red / acquire-ld) -------------
        if (tid == 0) {
            asm volatile("red.release.gpu.global.add.u32 [%0], 1;"
                         :: "l"(&g_ctr) : "memory");
            const unsigned target = (unsigned)(t + 1) * GBLK;
            unsigned c;
            do {
                asm volatile("ld.acquire.gpu.global.u32 %0, [%1];"
                             : "=r"(c) : "l"(&g_ctr));
            } while (c < target);
        }
        __syncthreads();                                 // bar D: release CTA
    }
}

// ---------------- kernel 3: out = states @ w_out^T + b_out ------------------
__global__ void proj_kernel(const float* __restrict__ w_out,
                            const float* __restrict__ b_out,
                            float* __restrict__ out) {
    __shared__ float s_sh[32][33];
    __shared__ float w_sh[DOUT][33];
    const int t0  = blockIdx.x * 32;
    const int tid = threadIdx.x;
    const int tx  = tid & 15;
    const int ty  = tid >> 4;
    float acc[2][4] = {};

    for (int kc = 0; kc < NRES; kc += 32) {
        for (int i = tid; i < 32 * 32; i += 256) {
            int r = i >> 5, k = i & 31;
            s_sh[r][k] = g_states[(size_t)(t0 + r) * NRES + kc + k];
        }
        for (int i = tid; i < DOUT * 32; i += 256) {
            int o = i >> 5, k = i & 31;
            w_sh[o][k] = w_out[(size_t)o * NRES + kc + k];
        }
        __syncthreads();
        for (int k = 0; k < 32; k++) {
            float sv[2], wv[4];
            #pragma unroll
            for (int i = 0; i < 2; i++) sv[i] = s_sh[ty * 2 + i][k];
            #pragma unroll
            for (int j = 0; j < 4; j++) wv[j] = w_sh[tx * 4 + j][k];
            #pragma unroll
            for (int i = 0; i < 2; i++)
                #pragma unroll
                for (int j = 0; j < 4; j++)
                    acc[i][j] += sv[i] * wv[j];
        }
        __syncthreads();
    }
    #pragma unroll
    for (int i = 0; i < 2; i++)
        #pragma unroll
        for (int j = 0; j < 4; j++)
            out[(size_t)(t0 + ty * 2 + i) * DOUT + tx * 4 + j] = acc[i][j] + b_out[tx * 4 + j];
}

// ---------------- launch ----------------------------------------------------
extern "C" void kernel_launch(void* const* d_in, const int* in_sizes, int n_in,
                              void* d_out, int out_size) {
    const float* u     = (const float*)d_in[0];  // (8192, 64)
    const float* noise = (const float*)d_in[1];  // (8192, 2048)
    const float* W_in  = (const float*)d_in[2];  // (2048, 64)
    const float* W     = (const float*)d_in[3];  // (2048, 2048)
    const float* w_out = (const float*)d_in[4];  // (64, 2048)
    const float* b_out = (const float*)d_in[5];  // (64,)
    float* out = (float*)d_out;                  // (8192, 64)

    init_kernel<<<NRES / 256, 256>>>();
    drive_kernel<<<dim3(NRES / 256, T_STEPS / TILE_T), 256>>>(u, noise, W_in);
    reservoir_kernel<<<GBLK, TPB>>>(W);
    proj_kernel<<<T_STEPS / 32, 256>>>(w_out, b_out, out);
}

// round 16
// speedup vs baseline: 1.0878x; 1.0059x over previous
#include <cuda_runtime.h>
#include <cstddef>

#define T_STEPS 8192
#define NRES    2048
#define DIN     64
#define DOUT    64
#define GBLK    128          // CTAs; 16 rows each
#define TPB     256
#define LEAK    0.3f
#define NOISE_L 0.01f
#define TILE_T  128

// ---------------- scratch (device globals: allocation-free) ----------------
__device__ float    g_drive [T_STEPS * NRES];   // 64 MB
__device__ float    g_states[T_STEPS * NRES];   // 64 MB
__device__ float    g_sbuf  [2][NRES];          // double-buffered reservoir state
__device__ unsigned g_ctr;                      // monotonic barrier counter

// ---------------- kernel 0: reset barrier + state (determinism) -------------
__global__ void init_kernel() {
    int i = blockIdx.x * blockDim.x + threadIdx.x;
    if (i < NRES) { g_sbuf[0][i] = 0.f; g_sbuf[1][i] = 0.f; }
    if (i == 0) g_ctr = 0u;
}

// ---------------- kernel 1: drive = u @ W_in^T + 0.01*noise -----------------
// v2: each thread owns TWO n-columns (halves LDS-per-output); 256 CTAs.
__global__ void __launch_bounds__(256) drive_kernel(const float* __restrict__ u,
                                                    const float* __restrict__ noise,
                                                    const float* __restrict__ W_in) {
    __shared__ float4 u_sh[TILE_T * (DIN / 4)];   // 128 t x 64 floats = 32 KB
    const int tid = threadIdx.x;
    const int na  = blockIdx.x * 512 + tid;       // first n-column
    const int nb  = na + 256;                     // second n-column
    const int t0  = blockIdx.y * TILE_T;

    float4 wa[DIN / 4], wb[DIN / 4];
    const float4* Wv = reinterpret_cast<const float4*>(W_in);
    #pragma unroll
    for (int j = 0; j < DIN / 4; j++) {
        wa[j] = Wv[(size_t)na * (DIN / 4) + j];
        wb[j] = Wv[(size_t)nb * (DIN / 4) + j];
    }

    const float4* uv = reinterpret_cast<const float4*>(u + (size_t)t0 * DIN);
    for (int i = tid; i < TILE_T * (DIN / 4); i += 256) u_sh[i] = uv[i];
    __syncthreads();

    for (int t = 0; t < TILE_T; t++) {
        float accA = 0.f, accB = 0.f;
        #pragma unroll
        for (int j = 0; j < DIN / 4; j++) {
            float4 uu = u_sh[t * (DIN / 4) + j];
            accA += wa[j].x * uu.x + wa[j].y * uu.y + wa[j].z * uu.z + wa[j].w * uu.w;
            accB += wb[j].x * uu.x + wb[j].y * uu.y + wb[j].z * uu.z + wb[j].w * uu.w;
        }
        size_t base = (size_t)(t0 + t) * NRES;
        g_drive[base + na] = accA + NOISE_L * noise[base + na];
        g_drive[base + nb] = accB + NOISE_L * noise[base + nb];
    }
}

// ---------------- kernel 2: persistent reservoir (R12/R15, proven best) -----
// Split-K: warp w owns cols [256w,256w+256); lane l: row l&15, half l>>4.
// Warp-private staging, broadcast-LDS f32x2 FMAs, warp-0 tree-reduce tail,
// 2 CTA barriers/step, single monotonic counter, release-red / acquire-ld,
// exactly 1 parked spinner per CTA. UNCHANGED from the reproduced plateau.
__global__ void __launch_bounds__(TPB, 1) reservoir_kernel(const float* __restrict__ W) {
    __shared__ float s_sh[8][272];            // per-warp slab: 2x(128 data + 8 pad)
    __shared__ float red_sh[2][8][17];        // parity-buffered warp partials

    const int tid  = threadIdx.x;
    const int cta  = blockIdx.x;
    const int warp = tid >> 5;
    const int lane = tid & 31;
    const int row  = lane & 15;               // local row 0..15
    const int half = lane >> 4;               // 0: cols +0..127, 1: +128..255
    const int grow = cta * 16 + row;          // global row of my partial

    const int c0 = warp * 256 + half * 128;
    const float4* Wv = reinterpret_cast<const float4*>(W + (size_t)grow * NRES + c0);
    unsigned long long wp[64];
    #pragma unroll
    for (int k = 0; k < 32; k++) {
        float4 a = Wv[k];
        wp[2*k]   = ((unsigned long long)__float_as_uint(a.y) << 32) | __float_as_uint(a.x);
        wp[2*k+1] = ((unsigned long long)__float_as_uint(a.w) << 32) | __float_as_uint(a.z);
    }

    const bool tail = (warp == 0) && (lane < 16);
    float sp   = 0.f;
    float dcur = 0.f;
    if (tail) dcur = g_drive[grow];

    float4* slab4 = reinterpret_cast<float4*>(s_sh[warp]);
    const int rdbase = 34 * half;

    #pragma unroll 1
    for (int t = 0; t < T_STEPS; t++) {
        // ---- warp-private stage: 2 coalesced 512B LDGs, STS, syncwarp ------
        const float4* sg = reinterpret_cast<const float4*>(g_sbuf[t & 1]) + warp * 64;
        float4 vA = __ldcg(sg + lane);
        float4 vB = __ldcg(sg + 32 + lane);
        slab4[lane]      = vA;
        slab4[34 + lane] = vB;
        __syncwarp();

        // ---- broadcast-LDS split-K partials (4 f32x2 chains) ---------------
        unsigned long long aA = 0, aB = 0, aC = 0, aD = 0;
        #pragma unroll
        for (int k = 0; k < 32; k += 2) {
            float4 sv  = slab4[rdbase + k];
            float4 sv2 = slab4[rdbase + k + 1];
            asm("{\n\t"
                ".reg .b64 p0, p1, p2, p3;\n\t"
                "mov.b64 p0, {%4, %5};\n\t"
                "mov.b64 p1, {%6, %7};\n\t"
                "mov.b64 p2, {%8, %9};\n\t"
                "mov.b64 p3, {%10, %11};\n\t"
                "fma.rn.f32x2 %0, %12, p0, %0;\n\t"
                "fma.rn.f32x2 %1, %13, p1, %1;\n\t"
                "fma.rn.f32x2 %2, %14, p2, %2;\n\t"
                "fma.rn.f32x2 %3, %15, p3, %3;\n\t"
                "}"
                : "+l"(aA), "+l"(aB), "+l"(aC), "+l"(aD)
                : "f"(sv.x), "f"(sv.y), "f"(sv.z), "f"(sv.w),
                  "f"(sv2.x), "f"(sv2.y), "f"(sv2.z), "f"(sv2.w),
                  "l"(wp[2*k]), "l"(wp[2*k+1]), "l"(wp[2*k+2]), "l"(wp[2*k+3]));
        }
        float e0, o0, e1, o1;
        asm("{\n\t.reg .b64 r0;\n\tadd.rn.f32x2 r0, %2, %3;\n\tmov.b64 {%0, %1}, r0;\n\t}"
            : "=f"(e0), "=f"(o0) : "l"(aA), "l"(aB));
        asm("{\n\t.reg .b64 r1;\n\tadd.rn.f32x2 r1, %2, %3;\n\tmov.b64 {%0, %1}, r1;\n\t}"
            : "=f"(e1), "=f"(o1) : "l"(aC), "l"(aD));
        float part = (e0 + o0) + (e1 + o1);
        part += __shfl_xor_sync(0xffffffffu, part, 16);

        const int par = t & 1;
        if (lane < 16) red_sh[par][warp][row] = part;
        __syncthreads();                                 // bar B

        // ---- tail: warp 0's 16 lanes tree-reduce 8 warps, update, publish --
        if (tail) {
            float p0 = red_sh[par][0][row], p1 = red_sh[par][1][row];
            float p2 = red_sh[par][2][row], p3 = red_sh[par][3][row];
            float p4 = red_sh[par][4][row], p5 = red_sh[par][5][row];
            float p6 = red_sh[par][6][row], p7 = red_sh[par][7][row];
            float sum = dcur + (((p0 + p1) + (p2 + p3)) + ((p4 + p5) + (p6 + p7)));
            float z  = __expf(2.f * sum);                // tanh = 1 - 2/(e^2x+1)
            float th = 1.f - __fdividef(2.f, z + 1.f);
            float ns = (1.f - LEAK) * sp + LEAK * th;
            sp = ns;
            g_sbuf[(t + 1) & 1][grow] = ns;              // coalesced 64B publish
            __stcs(&g_states[(size_t)t * NRES + grow], ns);
            if (t + 1 < T_STEPS)                         // prefetch under spin
                dcur = g_drive[(size_t)(t + 1) * NRES + grow];
        }
        __syncwarp();                                    // order warp-0 publishes

        // ---- monotonic grid barrier (release-red / acquire-ld) -------------
        if (tid == 0) {
            asm volatile("red.release.gpu.global.add.u32 [%0], 1;"
                         :: "l"(&g_ctr) : "memory");
            const unsigned target = (unsigned)(t + 1) * GBLK;
            unsigned c;
            do {
                asm volatile("ld.acquire.gpu.global.u32 %0, [%1];"
                             : "=r"(c) : "l"(&g_ctr));
            } while (c < target);
        }
        __syncthreads();                                 // bar D: release CTA
    }
}

// ---------------- kernel 3: out = states @ w_out^T + b_out ------------------
// v2: 64-row tiles, float4 gmem loads (MLP 4), pad-65 smem (wv conflict-free).
__global__ void __launch_bounds__(256) proj_kernel(const float* __restrict__ w_out,
                                                   const float* __restrict__ b_out,
                                                   float* __restrict__ out) {
    __shared__ float s_sh[64][65];            // 16.6 KB
    __shared__ float w_sh[DOUT][65];          // 16.6 KB
    const int t0  = blockIdx.x * 64;
    const int tid = threadIdx.x;
    const int tx  = tid & 15;                 // output group: 4 outs
    const int ty  = tid >> 4;                 // row group: 4 rows
    float acc[4][4] = {};

    for (int kc = 0; kc < NRES; kc += 64) {
        // states tile: 64 rows x 64 cols, float4 loads (4 per thread)
        for (int i = tid; i < 64 * 16; i += 256) {
            int r = i >> 4, c = i & 15;
            float4 v = *reinterpret_cast<const float4*>(
                &g_states[(size_t)(t0 + r) * NRES + kc + c * 4]);
            s_sh[r][c*4+0] = v.x; s_sh[r][c*4+1] = v.y;
            s_sh[r][c*4+2] = v.z; s_sh[r][c*4+3] = v.w;
        }
        // w tile: 64 outs x 64 cols, float4 loads
        for (int i = tid; i < DOUT * 16; i += 256) {
            int o = i >> 4, c = i & 15;
            float4 v = *reinterpret_cast<const float4*>(
                &w_out[(size_t)o * NRES + kc + c * 4]);
            w_sh[o][c*4+0] = v.x; w_sh[o][c*4+1] = v.y;
            w_sh[o][c*4+2] = v.z; w_sh[o][c*4+3] = v.w;
        }
        __syncthreads();
        for (int k = 0; k < 64; k++) {
            float sv[4], wv[4];
            #pragma unroll
            for (int i = 0; i < 4; i++) sv[i] = s_sh[ty * 4 + i][k];
            #pragma unroll
            for (int j = 0; j < 4; j++) wv[j] = w_sh[tx * 4 + j][k];
            #pragma unroll
            for (int i = 0; i < 4; i++)
                #pragma unroll
                for (int j = 0; j < 4; j++)
                    acc[i][j] += sv[i] * wv[j];
        }
        __syncthreads();
    }
    #pragma unroll
    for (int i = 0; i < 4; i++)
        #pragma unroll
        for (int j = 0; j < 4; j++)
            out[(size_t)(t0 + ty * 4 + i) * DOUT + tx * 4 + j] = acc[i][j] + b_out[tx * 4 + j];
}

// ---------------- launch ----------------------------------------------------
extern "C" void kernel_launch(void* const* d_in, const int* in_sizes, int n_in,
                              void* d_out, int out_size) {
    const float* u     = (const float*)d_in[0];  // (8192, 64)
    const float* noise = (const float*)d_in[1];  // (8192, 2048)
    const float* W_in  = (const float*)d_in[2];  // (2048, 64)
    const float* W     = (const float*)d_in[3];  // (2048, 2048)
    const float* w_out = (const float*)d_in[4];  // (64, 2048)
    const float* b_out = (const float*)d_in[5];  // (64,)
    float* out = (float*)d_out;                  // (8192, 64)

    init_kernel<<<NRES / 256, 256>>>();
    drive_kernel<<<dim3(NRES / 512, T_STEPS / TILE_T), 256>>>(u, noise, W_in);
    reservoir_kernel<<<GBLK, TPB>>>(W);
    proj_kernel<<<T_STEPS / 64, 256>>>(w_out, b_out, out);
}